// round 4
// baseline (speedup 1.0000x reference)
#include <cuda_runtime.h>

#define Bc 8
#define Pc 512
#define Dc 16
#define Ec 64
#define Hc 128

typedef unsigned long long u64;

// Scratch (no allocations allowed -> __device__ globals)
__device__ float g_a[Bc * Pc * Hc];     // a_s = ns @ We1[17:33]          (2 MB)
__device__ float g_c[Bc * Pc * Hc];     // c_r = nr @ We1[1:17] + be1     (2 MB)
__device__ float g_dist[Bc * Pc * Pc];  // dist[b][r][s]                  (8 MB)

// ---------------- packed f32x2 helpers (sm_103a) ----------------
__device__ __forceinline__ u64 add2(u64 a, u64 b) {
    u64 r; asm("add.rn.f32x2 %0,%1,%2;" : "=l"(r) : "l"(a), "l"(b)); return r;
}
__device__ __forceinline__ u64 fma2(u64 a, u64 b, u64 c) {
    u64 r; asm("fma.rn.f32x2 %0,%1,%2,%3;" : "=l"(r) : "l"(a), "l"(b), "l"(c)); return r;
}
__device__ __forceinline__ u64 pack2(float lo, float hi) {
    u64 r; asm("mov.b64 %0,{%1,%2};" : "=l"(r) : "f"(lo), "f"(hi)); return r;
}
__device__ __forceinline__ void unpack2(u64 x, float& lo, float& hi) {
    asm("mov.b64 {%0,%1},%2;" : "=f"(lo), "=f"(hi) : "l"(x));
}
__device__ __forceinline__ u64 relu2(u64 x) {
    float lo, hi; unpack2(x, lo, hi);
    return pack2(fmaxf(lo, 0.f), fmaxf(hi, 0.f));
}

// ---------------------------------------------------------------------------
// K1 (fused pre+dist): grid = (b, 16-receiver chunk) = 8*32, 256 threads.
// Stages the full node batch in smem, then computes:
//   - a,c for this chunk's 16 nodes (128 k-threads x 2 node-groups)
//   - dist rows for this chunk's 16 receivers vs all 512 senders
// ---------------------------------------------------------------------------
__global__ void __launch_bounds__(256)
predist_kernel(const float* __restrict__ h,
               const float* __restrict__ We1,
               const float* __restrict__ be1) {
    int b = blockIdx.x >> 5;
    int rc = blockIdx.x & 31;
    int t = threadIdx.x;

    __shared__ float nd[Pc][Dc + 1];  // 34.8 KB, pad kills conflicts

    for (int i = t; i < Pc * Dc; i += 256)
        nd[i >> 4][i & 15] = h[b * Pc * Dc + i];
    __syncthreads();

    // ---- a, c for nodes rc*16 .. rc*16+15 ----
    {
        int k = t & 127;
        int ng = t >> 7;               // 0/1 -> 8 nodes each
        int n0 = rc * 16 + ng * 8;
        float a[8], c[8];
        float b1 = be1[k];
#pragma unroll
        for (int n = 0; n < 8; n++) { a[n] = 0.f; c[n] = b1; }
#pragma unroll
        for (int d = 0; d < Dc; d++) {
            float ws = We1[(17 + d) * Hc + k];
            float wr = We1[(1 + d) * Hc + k];
#pragma unroll
            for (int n = 0; n < 8; n++) {
                float x = nd[n0 + n][d];
                a[n] = fmaf(x, ws, a[n]);
                c[n] = fmaf(x, wr, c[n]);
            }
        }
#pragma unroll
        for (int n = 0; n < 8; n++) {
            g_a[(b * Pc + n0 + n) * Hc + k] = a[n];
            g_c[(b * Pc + n0 + n) * Hc + k] = c[n];
        }
    }

    // ---- dist rows: 16 receivers x 512 senders ----
    for (int idx = t; idx < 16 * Pc; idx += 256) {
        int r = rc * 16 + (idx >> 9);
        int s = idx & (Pc - 1);
        float acc = 0.f;
#pragma unroll
        for (int d = 0; d < Dc; d++) {
            float df = nd[r][d] - nd[s][d];
            acc = fmaf(df, df, acc);
        }
        g_dist[(b * Pc + r) * Pc + s] = sqrtf(acc);
    }
}

// ---------------------------------------------------------------------------
// K2 (fused edge+post): grid = 512 (b, 8 receivers), 256 threads.
// Thread = (sender-quarter q[0..3], recv-group rg[0..1], k-quad tk[0..31]).
// Full 8x512 dist tile staged once (duplicated u64 pairs, 32 KB), main loop
// sync-free; cross-quarter reduce reuses the dist buffer; then the whole
// post-MLP runs in-block.
// ---------------------------------------------------------------------------
__global__ void __launch_bounds__(256, 3)
edgepost_kernel(const float* __restrict__ h,
                const float* __restrict__ We1,
                const float* __restrict__ We2,
                const float* __restrict__ be2,
                const float* __restrict__ Wn1,
                const float* __restrict__ bn1,
                const float* __restrict__ Wn2,
                const float* __restrict__ bn2,
                float* __restrict__ out) {
    int b = blockIdx.x >> 6;
    int r0 = (blockIdx.x & 63) * 8;
    int node0 = b * Pc + r0;
    int t = threadIdx.x;
    int tk = t & 31;           // k-quad: k = 4*tk .. 4*tk+3
    int rg = (t >> 5) & 1;     // receiver group (4 each)
    int q  = t >> 6;           // sender quarter (128 each)
    int k0 = tk * 4;

    __shared__ __align__(16) u64 sbig[8 * Pc];        // 32 KB: dist tile, then partials
#define SDIST(r, s)      sbig[(r) * Pc + (s)]
#define PBUF(qq, r, pr, x) sbig[((((qq) * 8 + (r)) * 2 + (pr)) << 5) + (x)]
    __shared__ __align__(16) float Hs[8][Hc];         // 4 KB
    __shared__ __align__(16) float nin[8][Ec + Dc];   // 2.5 KB
    __shared__ __align__(16) float hid[8][Hc];        // 4 KB

    u64 w0a = *(const u64*)(We1 + k0);
    u64 w0b = *(const u64*)(We1 + k0 + 2);

    u64 cra[4], crb[4], acca[4], accb[4];
#pragma unroll
    for (int n = 0; n < 4; n++) {
        const float* cp = g_c + (node0 + rg * 4 + n) * Hc + k0;
        cra[n] = *(const u64*)cp;
        crb[n] = *(const u64*)(cp + 2);
        acca[n] = 0ull;
        accb[n] = 0ull;
    }

    // ---- stage full dist tile: 8 recv x 512 senders, duplicated pairs ----
    {
        const float* drow = g_dist + (size_t)node0 * Pc;
        for (int i = t; i < 8 * Pc; i += 256) {
            float d = drow[(i >> 9) * Pc + (i & (Pc - 1))];
            sbig[i] = pack2(d, d);
        }
    }
    __syncthreads();

    // ---- main loop: 128 senders per thread, sync-free ----
    const float* arow = g_a + b * Pc * Hc + k0;
    int sbase = q * 128;
#pragma unroll 4
    for (int ss = 0; ss < 128; ss++) {
        int s = sbase + ss;
        float4 av = *(const float4*)(arow + s * Hc);
        u64 ava = pack2(av.x, av.y);
        u64 avb = pack2(av.z, av.w);
#pragma unroll
        for (int n = 0; n < 4; n++) {
            u64 d2 = SDIST(rg * 4 + n, s);
            u64 pa = fma2(d2, w0a, add2(ava, cra[n]));
            u64 pb = fma2(d2, w0b, add2(avb, crb[n]));
            acca[n] = add2(acca[n], relu2(pa));
            accb[n] = add2(accb[n], relu2(pb));
        }
    }

    // ---- cross-quarter reduce (reuse sbig) + exact self-term removal ----
    __syncthreads();
#pragma unroll
    for (int n = 0; n < 4; n++) {
        PBUF(q, rg * 4 + n, 0, tk) = acca[n];
        PBUF(q, rg * 4 + n, 1, tk) = accb[n];
    }
    __syncthreads();

#pragma unroll
    for (int j = 0; j < 2; j++) {
        int idx = t * 2 + j;          // 0..511
        int rcv = idx >> 6;
        int pr  = (idx >> 5) & 1;
        int tkx = idx & 31;
        u64 s = add2(add2(PBUF(0, rcv, pr, tkx), PBUF(1, rcv, pr, tkx)),
                     add2(PBUF(2, rcv, pr, tkx), PBUF(3, rcv, pr, tkx)));
        int kk = tkx * 4 + pr * 2;
        float lo, hi; unpack2(s, lo, hi);
        // s == r term: dist(r,r) == 0 exactly -> relu(a_r + c_r), exact
        const float* ap = g_a + (node0 + rcv) * Hc + kk;
        const float* cp = g_c + (node0 + rcv) * Hc + kk;
        Hs[rcv][kk]     = lo - fmaxf(ap[0] + cp[0], 0.f);
        Hs[rcv][kk + 1] = hi - fmaxf(ap[1] + cp[1], 0.f);
    }
    // node features into nin[:, 64:80]
    if (t < 128)
        nin[t >> 4][Ec + (t & 15)] = h[node0 * Dc + t];
    __syncthreads();

    // ---- Phase A: agg = hsum @ We2 + 511*be2.  thread = (j, node-pair) ----
    {
        int j = t & 63;
        int n0 = (t >> 6) * 2, n1 = n0 + 1;
        float b2 = 511.0f * be2[j];
        float a0 = b2, a1 = b2;
#pragma unroll 8
        for (int kk = 0; kk < Hc; kk += 4) {
            float w0 = We2[(kk + 0) * Ec + j];
            float w1 = We2[(kk + 1) * Ec + j];
            float w2 = We2[(kk + 2) * Ec + j];
            float w3 = We2[(kk + 3) * Ec + j];
            float4 v0 = *((const float4*)&Hs[n0][0] + (kk >> 2));
            float4 v1 = *((const float4*)&Hs[n1][0] + (kk >> 2));
            a0 = fmaf(v0.x, w0, a0); a0 = fmaf(v0.y, w1, a0);
            a0 = fmaf(v0.z, w2, a0); a0 = fmaf(v0.w, w3, a0);
            a1 = fmaf(v1.x, w0, a1); a1 = fmaf(v1.y, w1, a1);
            a1 = fmaf(v1.z, w2, a1); a1 = fmaf(v1.w, w3, a1);
        }
        nin[n0][j] = a0;
        nin[n1][j] = a1;
    }
    __syncthreads();

    // ---- Phase B: hidden layer. thread = (hidden unit, node-half) ----
    {
        int hu = t & 127, g = t >> 7;
        float b1 = bn1[hu];
        float accs[4];
#pragma unroll
        for (int m = 0; m < 4; m++) accs[m] = b1;
#pragma unroll 5
        for (int i = 0; i < Ec + Dc; i += 4) {
            float w0 = Wn1[(i + 0) * Hc + hu];
            float w1 = Wn1[(i + 1) * Hc + hu];
            float w2 = Wn1[(i + 2) * Hc + hu];
            float w3 = Wn1[(i + 3) * Hc + hu];
#pragma unroll
            for (int m = 0; m < 4; m++) {
                float4 v = *((const float4*)&nin[g * 4 + m][0] + (i >> 2));
                accs[m] = fmaf(v.x, w0, accs[m]);
                accs[m] = fmaf(v.y, w1, accs[m]);
                accs[m] = fmaf(v.z, w2, accs[m]);
                accs[m] = fmaf(v.w, w3, accs[m]);
            }
        }
#pragma unroll
        for (int m = 0; m < 4; m++)
            hid[g * 4 + m][hu] = fmaxf(accs[m], 0.f);
    }
    __syncthreads();

    // ---- Phase C: output layer. 128 threads = (node, dim) ----
    if (t < 128) {
        int n = t >> 4, d = t & 15;
        float a0 = 0.f, a1 = 0.f, a2 = 0.f, a3 = 0.f;
#pragma unroll 8
        for (int kk = 0; kk < Hc; kk += 4) {
            float4 v = *((const float4*)&hid[n][0] + (kk >> 2));
            a0 = fmaf(v.x, Wn2[(kk + 0) * Dc + d], a0);
            a1 = fmaf(v.y, Wn2[(kk + 1) * Dc + d], a1);
            a2 = fmaf(v.z, Wn2[(kk + 2) * Dc + d], a2);
            a3 = fmaf(v.w, Wn2[(kk + 3) * Dc + d], a3);
        }
        out[node0 * Dc + t] = bn2[d] + ((a0 + a1) + (a2 + a3));
    }
#undef SDIST
#undef PBUF
}

// ---------------------------------------------------------------------------
extern "C" void kernel_launch(void* const* d_in, const int* in_sizes, int n_in,
                              void* d_out, int out_size) {
    const float* h   = (const float*)d_in[0];
    const float* We1 = (const float*)d_in[1];
    const float* be1 = (const float*)d_in[2];
    const float* We2 = (const float*)d_in[3];
    const float* be2 = (const float*)d_in[4];
    const float* Wn1 = (const float*)d_in[5];
    const float* bn1 = (const float*)d_in[6];
    const float* Wn2 = (const float*)d_in[7];
    const float* bn2 = (const float*)d_in[8];
    float* out = (float*)d_out;

    predist_kernel<<<Bc * 32, 256>>>(h, We1, be1);
    edgepost_kernel<<<Bc * 64, 256>>>(h, We1, We2, be2, Wn1, bn1, Wn2, bn2, out);
}

// round 5
// speedup vs baseline: 1.0903x; 1.0903x over previous
#include <cuda_runtime.h>

#define Bc 8
#define Pc 512
#define Dc 16
#define Ec 64
#define Hc 128

typedef unsigned long long u64;

// Scratch (no allocations allowed -> __device__ globals)
__device__ float g_a[Bc * Pc * Hc];     // a_s = ns @ We1[17:33]          (2 MB)
__device__ float g_c[Bc * Pc * Hc];     // c_r = nr @ We1[1:17] + be1     (2 MB)
__device__ float g_dist[Bc * Pc * Pc];  // dist[b][r][s]                  (8 MB)

// ---------------- packed f32x2 helpers (sm_103a) ----------------
__device__ __forceinline__ u64 add2(u64 a, u64 b) {
    u64 r; asm("add.rn.f32x2 %0,%1,%2;" : "=l"(r) : "l"(a), "l"(b)); return r;
}
__device__ __forceinline__ u64 fma2(u64 a, u64 b, u64 c) {
    u64 r; asm("fma.rn.f32x2 %0,%1,%2,%3;" : "=l"(r) : "l"(a), "l"(b), "l"(c)); return r;
}
__device__ __forceinline__ u64 pack2(float lo, float hi) {
    u64 r; asm("mov.b64 %0,{%1,%2};" : "=l"(r) : "f"(lo), "f"(hi)); return r;
}
__device__ __forceinline__ void unpack2(u64 x, float& lo, float& hi) {
    asm("mov.b64 {%0,%1},%2;" : "=f"(lo), "=f"(hi) : "l"(x));
}
__device__ __forceinline__ u64 relu2(u64 x) {
    float lo, hi; unpack2(x, lo, hi);
    return pack2(fmaxf(lo, 0.f), fmaxf(hi, 0.f));
}

// ---------------------------------------------------------------------------
// K1 (fused pre+dist): grid = (b, 16-receiver chunk) = 8*32, 256 threads.
// ---------------------------------------------------------------------------
__global__ void __launch_bounds__(256)
predist_kernel(const float* __restrict__ h,
               const float* __restrict__ We1,
               const float* __restrict__ be1) {
    int b = blockIdx.x >> 5;
    int rc = blockIdx.x & 31;
    int t = threadIdx.x;

    __shared__ float nd[Pc][Dc + 1];  // 34.8 KB, pad kills conflicts

    for (int i = t; i < Pc * Dc; i += 256)
        nd[i >> 4][i & 15] = h[b * Pc * Dc + i];
    __syncthreads();

    // ---- a, c for nodes rc*16 .. rc*16+15 ----
    {
        int k = t & 127;
        int ng = t >> 7;               // 0/1 -> 8 nodes each
        int n0 = rc * 16 + ng * 8;
        float a[8], c[8];
        float b1 = be1[k];
#pragma unroll
        for (int n = 0; n < 8; n++) { a[n] = 0.f; c[n] = b1; }
#pragma unroll
        for (int d = 0; d < Dc; d++) {
            float ws = We1[(17 + d) * Hc + k];
            float wr = We1[(1 + d) * Hc + k];
#pragma unroll
            for (int n = 0; n < 8; n++) {
                float x = nd[n0 + n][d];
                a[n] = fmaf(x, ws, a[n]);
                c[n] = fmaf(x, wr, c[n]);
            }
        }
#pragma unroll
        for (int n = 0; n < 8; n++) {
            g_a[(b * Pc + n0 + n) * Hc + k] = a[n];
            g_c[(b * Pc + n0 + n) * Hc + k] = c[n];
        }
    }

    // ---- dist rows: 16 receivers x 512 senders ----
    for (int idx = t; idx < 16 * Pc; idx += 256) {
        int r = rc * 16 + (idx >> 9);
        int s = idx & (Pc - 1);
        float acc = 0.f;
#pragma unroll
        for (int d = 0; d < Dc; d++) {
            float df = nd[r][d] - nd[s][d];
            acc = fmaf(df, df, acc);
        }
        g_dist[(b * Pc + r) * Pc + s] = sqrtf(acc);
    }
}

// ---------------------------------------------------------------------------
// K2 (fused edge+post): grid = 512 (b, 8 receivers), 256 threads.
// Thread = (sender-quarter q[0..3], recv-group rg[0..1], k-quad tk[0..31]).
// __launch_bounds__(256, 4): all 512 blocks resident in ONE wave (592 slots).
// Main loop software-pipelines the av LDG.128 one iteration ahead.
// ---------------------------------------------------------------------------
__global__ void __launch_bounds__(256, 4)
edgepost_kernel(const float* __restrict__ h,
                const float* __restrict__ We1,
                const float* __restrict__ We2,
                const float* __restrict__ be2,
                const float* __restrict__ Wn1,
                const float* __restrict__ bn1,
                const float* __restrict__ Wn2,
                const float* __restrict__ bn2,
                float* __restrict__ out) {
    int b = blockIdx.x >> 6;
    int r0 = (blockIdx.x & 63) * 8;
    int node0 = b * Pc + r0;
    int t = threadIdx.x;
    int tk = t & 31;           // k-quad: k = 4*tk .. 4*tk+3
    int rg = (t >> 5) & 1;     // receiver group (4 each)
    int q  = t >> 6;           // sender quarter (128 each)
    int k0 = tk * 4;

    __shared__ __align__(16) u64 sbig[8 * Pc];        // 32 KB: dist tile, then partials
#define PBUF(qq, r, pr, x) sbig[((((qq) * 8 + (r)) * 2 + (pr)) << 5) + (x)]
    __shared__ __align__(16) float Hs[8][Hc];         // 4 KB
    __shared__ __align__(16) float nin[8][Ec + Dc];   // 2.5 KB
    __shared__ __align__(16) float hid[8][Hc];        // 4 KB

    u64 w0a = *(const u64*)(We1 + k0);
    u64 w0b = *(const u64*)(We1 + k0 + 2);

    u64 cra[4], crb[4], acca[4], accb[4];
#pragma unroll
    for (int n = 0; n < 4; n++) {
        const float* cp = g_c + (node0 + rg * 4 + n) * Hc + k0;
        cra[n] = *(const u64*)cp;
        crb[n] = *(const u64*)(cp + 2);
        acca[n] = 0ull;
        accb[n] = 0ull;
    }

    // ---- stage full dist tile: 8 recv x 512 senders, duplicated pairs ----
    {
        const float* drow = g_dist + (size_t)node0 * Pc;
#pragma unroll
        for (int j = 0; j < 16; j++) {
            int i = t + j * 256;
            float d = drow[(i >> 9) * Pc + (i & (Pc - 1))];
            sbig[i] = pack2(d, d);
        }
    }
    __syncthreads();

    // ---- main loop: 128 senders per thread, sync-free, av prefetched ----
    const float* arow = g_a + (b * Pc + q * 128) * Hc + k0;
    const u64* dbase = sbig + rg * 4 * Pc + q * 128;

    float4 av = *(const float4*)arow;
#pragma unroll 4
    for (int ss = 0; ss < 128; ss++) {
        float4 nxt;
        if (ss < 127) nxt = *(const float4*)(arow + (ss + 1) * Hc);
        u64 ava = pack2(av.x, av.y);
        u64 avb = pack2(av.z, av.w);
#pragma unroll
        for (int n = 0; n < 4; n++) {
            u64 d2 = dbase[n * Pc + ss];
            u64 pa = fma2(d2, w0a, add2(ava, cra[n]));
            u64 pb = fma2(d2, w0b, add2(avb, crb[n]));
            acca[n] = add2(acca[n], relu2(pa));
            accb[n] = add2(accb[n], relu2(pb));
        }
        av = nxt;
    }

    // ---- cross-quarter reduce (reuse sbig) + exact self-term removal ----
    __syncthreads();
#pragma unroll
    for (int n = 0; n < 4; n++) {
        PBUF(q, rg * 4 + n, 0, tk) = acca[n];
        PBUF(q, rg * 4 + n, 1, tk) = accb[n];
    }
    __syncthreads();

#pragma unroll
    for (int j = 0; j < 2; j++) {
        int idx = t * 2 + j;          // 0..511
        int rcv = idx >> 6;
        int pr  = (idx >> 5) & 1;
        int tkx = idx & 31;
        u64 s = add2(add2(PBUF(0, rcv, pr, tkx), PBUF(1, rcv, pr, tkx)),
                     add2(PBUF(2, rcv, pr, tkx), PBUF(3, rcv, pr, tkx)));
        int kk = tkx * 4 + pr * 2;
        float lo, hi; unpack2(s, lo, hi);
        // s == r term: dist(r,r) == 0 exactly -> relu(a_r + c_r), exact
        const float* ap = g_a + (node0 + rcv) * Hc + kk;
        const float* cp = g_c + (node0 + rcv) * Hc + kk;
        Hs[rcv][kk]     = lo - fmaxf(ap[0] + cp[0], 0.f);
        Hs[rcv][kk + 1] = hi - fmaxf(ap[1] + cp[1], 0.f);
    }
    // node features into nin[:, 64:80]
    if (t < 128)
        nin[t >> 4][Ec + (t & 15)] = h[node0 * Dc + t];
    __syncthreads();

    // ---- Phase A: agg = hsum @ We2 + 511*be2.  thread = (j, node-pair) ----
    {
        int j = t & 63;
        int n0 = (t >> 6) * 2, n1 = n0 + 1;
        float b2 = 511.0f * be2[j];
        float a0 = b2, a1 = b2;
#pragma unroll 8
        for (int kk = 0; kk < Hc; kk += 4) {
            float w0 = We2[(kk + 0) * Ec + j];
            float w1 = We2[(kk + 1) * Ec + j];
            float w2 = We2[(kk + 2) * Ec + j];
            float w3 = We2[(kk + 3) * Ec + j];
            float4 v0 = *((const float4*)&Hs[n0][0] + (kk >> 2));
            float4 v1 = *((const float4*)&Hs[n1][0] + (kk >> 2));
            a0 = fmaf(v0.x, w0, a0); a0 = fmaf(v0.y, w1, a0);
            a0 = fmaf(v0.z, w2, a0); a0 = fmaf(v0.w, w3, a0);
            a1 = fmaf(v1.x, w0, a1); a1 = fmaf(v1.y, w1, a1);
            a1 = fmaf(v1.z, w2, a1); a1 = fmaf(v1.w, w3, a1);
        }
        nin[n0][j] = a0;
        nin[n1][j] = a1;
    }
    __syncthreads();

    // ---- Phase B: hidden layer. thread = (hidden unit, node-half) ----
    {
        int hu = t & 127, g = t >> 7;
        float b1 = bn1[hu];
        float accs[4];
#pragma unroll
        for (int m = 0; m < 4; m++) accs[m] = b1;
#pragma unroll 5
        for (int i = 0; i < Ec + Dc; i += 4) {
            float w0 = Wn1[(i + 0) * Hc + hu];
            float w1 = Wn1[(i + 1) * Hc + hu];
            float w2 = Wn1[(i + 2) * Hc + hu];
            float w3 = Wn1[(i + 3) * Hc + hu];
#pragma unroll
            for (int m = 0; m < 4; m++) {
                float4 v = *((const float4*)&nin[g * 4 + m][0] + (i >> 2));
                accs[m] = fmaf(v.x, w0, accs[m]);
                accs[m] = fmaf(v.y, w1, accs[m]);
                accs[m] = fmaf(v.z, w2, accs[m]);
                accs[m] = fmaf(v.w, w3, accs[m]);
            }
        }
#pragma unroll
        for (int m = 0; m < 4; m++)
            hid[g * 4 + m][hu] = fmaxf(accs[m], 0.f);
    }
    __syncthreads();

    // ---- Phase C: output layer. 128 threads = (node, dim) ----
    if (t < 128) {
        int n = t >> 4, d = t & 15;
        float a0 = 0.f, a1 = 0.f, a2 = 0.f, a3 = 0.f;
#pragma unroll 8
        for (int kk = 0; kk < Hc; kk += 4) {
            float4 v = *((const float4*)&hid[n][0] + (kk >> 2));
            a0 = fmaf(v.x, Wn2[(kk + 0) * Dc + d], a0);
            a1 = fmaf(v.y, Wn2[(kk + 1) * Dc + d], a1);
            a2 = fmaf(v.z, Wn2[(kk + 2) * Dc + d], a2);
            a3 = fmaf(v.w, Wn2[(kk + 3) * Dc + d], a3);
        }
        out[node0 * Dc + t] = bn2[d] + ((a0 + a1) + (a2 + a3));
    }
#undef PBUF
}

// ---------------------------------------------------------------------------
extern "C" void kernel_launch(void* const* d_in, const int* in_sizes, int n_in,
                              void* d_out, int out_size) {
    const float* h   = (const float*)d_in[0];
    const float* We1 = (const float*)d_in[1];
    const float* be1 = (const float*)d_in[2];
    const float* We2 = (const float*)d_in[3];
    const float* be2 = (const float*)d_in[4];
    const float* Wn1 = (const float*)d_in[5];
    const float* bn1 = (const float*)d_in[6];
    const float* Wn2 = (const float*)d_in[7];
    const float* bn2 = (const float*)d_in[8];
    float* out = (float*)d_out;

    predist_kernel<<<Bc * 32, 256>>>(h, We1, be1);
    edgepost_kernel<<<Bc * 64, 256>>>(h, We1, We2, be2, Wn1, bn1, Wn2, bn2, out);
}